// round 16
// baseline (speedup 1.0000x reference)
#include <cuda_runtime.h>
#include <cuda_bf16.h>
#include <cstdint>
#include <math.h>

// Problem constants
#define R_DIM 128
#define C_DIM 256
#define E_DIM 768
#define H_DIM 12
#define D_DIM 64
#define M_TOK (R_DIM * C_DIM)          // 32768
#define SCALING 0.125f
#define NW_ELEM (E_DIM * E_DIM)

// bf16 hi/lo scratch (device globals; no allocation)
__device__ __align__(128) __nv_bfloat16 g_xh[M_TOK * E_DIM];
__device__ __align__(128) __nv_bfloat16 g_xl[M_TOK * E_DIM];
__device__ __align__(128) __nv_bfloat16 g_qh[M_TOK * E_DIM];
__device__ __align__(128) __nv_bfloat16 g_ql[M_TOK * E_DIM];
__device__ __align__(128) __nv_bfloat16 g_kh[M_TOK * E_DIM];
__device__ __align__(128) __nv_bfloat16 g_kl[M_TOK * E_DIM];
__device__ __align__(128) __nv_bfloat16 g_vh[M_TOK * E_DIM];
__device__ __align__(128) __nv_bfloat16 g_vl[M_TOK * E_DIM];
__device__ __align__(128) __nv_bfloat16 g_ch[M_TOK * E_DIM];
__device__ __align__(128) __nv_bfloat16 g_cl[M_TOK * E_DIM];
__device__ __align__(128) __nv_bfloat16 g_wh[4][NW_ELEM];
__device__ __align__(128) __nv_bfloat16 g_wl[4][NW_ELEM];
// column-mean of x for masked columns (bf16 split), indexed by column c
__device__ __align__(128) __nv_bfloat16 g_xbh[C_DIM * E_DIM];
__device__ __align__(128) __nv_bfloat16 g_xbl[C_DIM * E_DIM];

// mask compaction (device-side; deterministic prefix scan)
__device__ int g_cmap_u[256];
__device__ int g_cmap_m[256];
__device__ int g_nu;
__device__ int g_nm;

// ---------------------------------------------------------------------------
// Helpers
// ---------------------------------------------------------------------------
__device__ __forceinline__ uint32_t smem_u32(const void* p) {
    uint32_t a;
    asm("{ .reg .u64 t; cvta.to.shared.u64 t, %1; cvt.u32.u64 %0, t; }" : "=r"(a) : "l"(p));
    return a;
}
__device__ __forceinline__ void cp_async16(uint32_t s, const void* g) {
    size_t ga = __cvta_generic_to_global(g);
    asm volatile("cp.async.cg.shared.global [%0], [%1], 16;" :: "r"(s), "l"(ga));
}
__device__ __forceinline__ void cp_commit() { asm volatile("cp.async.commit_group;" ::: "memory"); }
template <int N> __device__ __forceinline__ void cp_wait() {
    asm volatile("cp.async.wait_group %0;" :: "n"(N) : "memory");
}
__device__ __forceinline__ void ldmx4(uint32_t* r, uint32_t addr) {
    asm volatile("ldmatrix.sync.aligned.m8n8.x4.shared.b16 {%0,%1,%2,%3}, [%4];"
        : "=r"(r[0]), "=r"(r[1]), "=r"(r[2]), "=r"(r[3]) : "r"(addr));
}
__device__ __forceinline__ void ldmx4t(uint32_t* r, uint32_t addr) {
    asm volatile("ldmatrix.sync.aligned.m8n8.x4.trans.shared.b16 {%0,%1,%2,%3}, [%4];"
        : "=r"(r[0]), "=r"(r[1]), "=r"(r[2]), "=r"(r[3]) : "r"(addr));
}
__device__ __forceinline__ void mma16816(float* c, const uint32_t* a, const uint32_t* b) {
    asm volatile("mma.sync.aligned.m16n8k16.row.col.f32.bf16.bf16.f32 "
        "{%0,%1,%2,%3}, {%4,%5,%6,%7}, {%8,%9}, {%0,%1,%2,%3};"
        : "+f"(c[0]), "+f"(c[1]), "+f"(c[2]), "+f"(c[3])
        : "r"(a[0]), "r"(a[1]), "r"(a[2]), "r"(a[3]), "r"(b[0]), "r"(b[1]));
}
__device__ __forceinline__ void split2(float f0, float f1, uint32_t& hi, uint32_t& lo) {
    __nv_bfloat16 h0 = __float2bfloat16(f0);
    __nv_bfloat16 h1 = __float2bfloat16(f1);
    __nv_bfloat16 l0 = __float2bfloat16(f0 - __bfloat162float(h0));
    __nv_bfloat16 l1 = __float2bfloat16(f1 - __bfloat162float(h1));
    __nv_bfloat162 hp = { h0, h1 }, lp = { l0, l1 };
    hi = *(uint32_t*)&hp;
    lo = *(uint32_t*)&lp;
}
__device__ __forceinline__ void stg_cs_f2(float* p, float a, float b) {
    asm volatile("st.global.cs.v2.f32 [%0], {%1, %2};" :: "l"(p), "f"(a), "f"(b));
}
__device__ __forceinline__ void stg_cs_f4(float* p, float a, float b, float c, float d) {
    asm volatile("st.global.cs.v4.f32 [%0], {%1, %2, %3, %4};"
        :: "l"(p), "f"(a), "f"(b), "f"(c), "f"(d));
}

#define SMEM_SWZ(o) ((o) ^ (((o) >> 3) & 0x70))

// ---------------------------------------------------------------------------
// Mask prep: deterministic Hillis-Steele scan, 1 block x 256 threads.
// ---------------------------------------------------------------------------
__global__ void prep_mask_kernel(const int* __restrict__ mask) {
    __shared__ int pu[256], pm[256];
    const int c = threadIdx.x;
    const int mu = (mask[c] == 0) ? 1 : 0;
    pu[c] = mu;
    pm[c] = 1 - mu;
    __syncthreads();
    for (int off = 1; off < 256; off <<= 1) {
        int vu = (c >= off) ? pu[c - off] : 0;
        int vm = (c >= off) ? pm[c - off] : 0;
        __syncthreads();
        pu[c] += vu;
        pm[c] += vm;
        __syncthreads();
    }
    if (mu) g_cmap_u[pu[c] - 1] = c;
    else    g_cmap_m[pm[c] - 1] = c;
    if (c == 255) { g_nu = pu[255]; g_nm = pm[255]; }
}

// ---------------------------------------------------------------------------
// Masked probs fill: probs[h][c][:][:] = 1/128 exactly (stream B).
// ---------------------------------------------------------------------------
__global__ __launch_bounds__(256) void probs_fill_kernel(
    const int* __restrict__ mask, float* __restrict__ probs)
{
    const int c = blockIdx.x;
    if (mask[c] == 0) return;
    const int hh = blockIdx.y;
    const float u = 0.0078125f;
    float* base = probs + ((size_t)hh * C_DIM + c) * 16384;
#pragma unroll
    for (int i = 0; i < 16; i++)
        stg_cs_f4(base + (threadIdx.x + i * 256) * 4, u, u, u, u);
}

// ---------------------------------------------------------------------------
// xbar: column mean of x over rows, for masked columns only -> bf16 split.
// ---------------------------------------------------------------------------
__global__ __launch_bounds__(256) void xbar_kernel(
    const float* __restrict__ x, const int* __restrict__ mask,
    __nv_bfloat16* __restrict__ xbh, __nv_bfloat16* __restrict__ xbl)
{
    const int c = blockIdx.x;
    if (mask[c] == 0) return;
    const int t = threadIdx.x;
#pragma unroll
    for (int u = 0; u < 3; u++) {
        const int d = t + u * 256;
        float s = 0.0f;
        for (int r = 0; r < R_DIM; r++)
            s += x[((size_t)r * C_DIM + c) * E_DIM + d];
        s *= 0.0078125f;
        __nv_bfloat16 h = __float2bfloat16(s);
        __nv_bfloat16 l = __float2bfloat16(s - __bfloat162float(h));
        xbh[(size_t)c * E_DIM + d] = h;
        xbl[(size_t)c * E_DIM + d] = l;
    }
}

// ---------------------------------------------------------------------------
// Merged split: x (unmasked-column tokens only) + 4 weights, grid-stride.
// ---------------------------------------------------------------------------
#define NX_ELEM (M_TOK * E_DIM)
#define NX4 (NX_ELEM / 4)
#define NW4 (NW_ELEM / 4)
#define NTOT4 (NX4 + 4 * NW4)
#define TOK_F4 (E_DIM / 4)              // 192 float4 per token

__device__ __forceinline__ void split_store(const float* __restrict__ in,
                                            __nv_bfloat16* __restrict__ hi,
                                            __nv_bfloat16* __restrict__ lo, int i)
{
    float4 v = ((const float4*)in)[i];
    __nv_bfloat16 h[4], l[4];
    h[0] = __float2bfloat16(v.x); l[0] = __float2bfloat16(v.x - __bfloat162float(h[0]));
    h[1] = __float2bfloat16(v.y); l[1] = __float2bfloat16(v.y - __bfloat162float(h[1]));
    h[2] = __float2bfloat16(v.z); l[2] = __float2bfloat16(v.z - __bfloat162float(h[2]));
    h[3] = __float2bfloat16(v.w); l[3] = __float2bfloat16(v.w - __bfloat162float(h[3]));
    ((uint2*)hi)[i] = *(uint2*)h;
    ((uint2*)lo)[i] = *(uint2*)l;
}

__global__ __launch_bounds__(256) void split_all_kernel(
    const float* __restrict__ x, const int* __restrict__ mask,
    const float* __restrict__ w0, const float* __restrict__ w1,
    const float* __restrict__ w2, const float* __restrict__ w3,
    __nv_bfloat16* __restrict__ xh, __nv_bfloat16* __restrict__ xl,
    __nv_bfloat16* __restrict__ whb, __nv_bfloat16* __restrict__ wlb)
{
    __shared__ unsigned char msk[256];
    if (threadIdx.x < 256) msk[threadIdx.x] = (mask[threadIdx.x] != 0);
    __syncthreads();

    const float* wsrc[4] = { w0, w1, w2, w3 };
    for (int i = blockIdx.x * blockDim.x + threadIdx.x; i < NTOT4; i += gridDim.x * blockDim.x) {
        if (i < NX4) {
            const int tok = i / TOK_F4;
            if (msk[tok & 255]) continue;
            split_store(x, xh, xl, i);
        } else {
            int j = i - NX4;
            int b = j / NW4, r = j - b * NW4;
            split_store(wsrc[b], whb + (size_t)b * NW_ELEM, wlb + (size_t)b * NW_ELEM, r);
        }
    }
}

// ---------------------------------------------------------------------------
// mma.sync GEMM body (unchanged)
// ---------------------------------------------------------------------------
#define GK 768
#define BM 128
#define BN 64
#define BK 64
#define NCHUNK (GK / BK)                 // 12
#define ABUF_BYTES (128 * 128)           // 16384
#define BBUF_BYTES (64 * 128)            // 8192
#define STAGE_BYTES (2 * ABUF_BYTES + 2 * BBUF_BYTES)   // 49152
#define GEMM_SMEM (2 * STAGE_BYTES + 1024)

template <bool GATHER>
__device__ __forceinline__ void load_chunk(
    uint32_t stage,
    const __nv_bfloat16* __restrict__ Ah, const __nv_bfloat16* __restrict__ Al,
    const __nv_bfloat16* __restrict__ Bh, const __nv_bfloat16* __restrict__ Bl,
    int tok_base, int tok_stride, const int* __restrict__ gather,
    int n0, int kc, int t)
{
#pragma unroll
    for (int p = 0; p < 4; p++) {
        int u = t + p * 256;
        int row = u >> 3, seg = u & 7;
        int tok = GATHER ? gather[row] : (tok_base + row * tok_stride);
        size_t go = (size_t)tok * GK + kc + seg * 8;
        uint32_t so = SMEM_SWZ(row * 128 + seg * 16);
        cp_async16(stage + so, Ah + go);
        cp_async16(stage + ABUF_BYTES + so, Al + go);
    }
#pragma unroll
    for (int p = 0; p < 2; p++) {
        int u = t + p * 256;
        int row = u >> 3, seg = u & 7;
        size_t go = (size_t)(n0 + row) * GK + kc + seg * 8;
        uint32_t so = SMEM_SWZ(row * 128 + seg * 16);
        cp_async16(stage + 2 * ABUF_BYTES + so, Bh + go);
        cp_async16(stage + 2 * ABUF_BYTES + BBUF_BYTES + so, Bl + go);
    }
}

template <bool SPLIT_OUT, bool GATHER>
__device__ __forceinline__ void gemm_body(
    const __nv_bfloat16* __restrict__ Ah, const __nv_bfloat16* __restrict__ Al,
    const __nv_bfloat16* __restrict__ Bh, const __nv_bfloat16* __restrict__ Bl,
    const float* __restrict__ bias, float* __restrict__ C,
    __nv_bfloat16* __restrict__ Ch, __nv_bfloat16* __restrict__ Cl,
    float scale, int tok_base, int tok_stride,
    const int* __restrict__ gather, int valid, int n0)
{
    extern __shared__ char smbuf[];
    const uint32_t tiles = (smem_u32(smbuf) + 1023) & ~1023u;
    const int t = threadIdx.x;
    const int lane = t & 31, wid = t >> 5;
    const int wm = wid >> 1, wn = wid & 1;

    const uint32_t stg[2] = { tiles, tiles + STAGE_BYTES };

    const int a_row = lane & 15;
    const int a_k8 = (lane >> 4) * 8;
    const int b_row = (lane & 7) + ((lane >> 4) & 1) * 8;
    const int b_k8 = ((lane >> 3) & 1) * 8;

    float acc[2][4][4];
#pragma unroll
    for (int mt = 0; mt < 2; mt++)
#pragma unroll
        for (int nt = 0; nt < 4; nt++)
#pragma unroll
            for (int q = 0; q < 4; q++) acc[mt][nt][q] = 0.0f;

    load_chunk<GATHER>(stg[0], Ah, Al, Bh, Bl, tok_base, tok_stride, gather, n0, 0, t);
    cp_commit();

    for (int c = 0; c < NCHUNK; c++) {
        const int s = c & 1;
        cp_wait<0>();
        __syncthreads();
        if (c + 1 < NCHUNK) {
            load_chunk<GATHER>(stg[s ^ 1], Ah, Al, Bh, Bl, tok_base, tok_stride, gather,
                               n0, (c + 1) * BK, t);
            cp_commit();
        }

        const uint32_t Abase = stg[s];
        const uint32_t Bbase = stg[s] + 2 * ABUF_BYTES;
#pragma unroll
        for (int kk = 0; kk < 4; kk++) {
            uint32_t ah[2][4], al[2][4];
#pragma unroll
            for (int mt = 0; mt < 2; mt++) {
                uint32_t off = (uint32_t)(wm * 32 + mt * 16 + a_row) * 128
                             + (kk * 16 + a_k8) * 2;
                uint32_t sw = SMEM_SWZ(off);
                ldmx4(ah[mt], Abase + sw);
                ldmx4(al[mt], Abase + ABUF_BYTES + sw);
            }
            uint32_t bh[2][4], bl[2][4];
#pragma unroll
            for (int nb = 0; nb < 2; nb++) {
                uint32_t off = (uint32_t)(wn * 32 + nb * 16 + b_row) * 128
                             + (kk * 16 + b_k8) * 2;
                uint32_t sw = SMEM_SWZ(off);
                ldmx4(bh[nb], Bbase + sw);
                ldmx4(bl[nb], Bbase + BBUF_BYTES + sw);
            }
#pragma unroll
            for (int mt = 0; mt < 2; mt++)
#pragma unroll
                for (int nt = 0; nt < 4; nt++) {
                    const uint32_t* fh = &bh[nt >> 1][(nt & 1) * 2];
                    const uint32_t* fl = &bl[nt >> 1][(nt & 1) * 2];
                    mma16816(acc[mt][nt], ah[mt], fh);
                    mma16816(acc[mt][nt], ah[mt], fl);
                    mma16816(acc[mt][nt], al[mt], fh);
                }
        }
    }

    // epilogue
#pragma unroll
    for (int mt = 0; mt < 2; mt++) {
        const int mrow = wm * 32 + mt * 16 + (lane >> 2);
#pragma unroll
        for (int half = 0; half < 2; half++) {
            const int rr = mrow + half * 8;
            const int tok = GATHER ? gather[rr] : (tok_base + rr * tok_stride);
            const bool ok = !GATHER || (rr < valid);
#pragma unroll
            for (int nt = 0; nt < 4; nt++) {
                const int n = n0 + wn * 32 + nt * 8 + (lane & 3) * 2;
                const float b0 = bias[n], b1 = bias[n + 1];
                float v0 = (acc[mt][nt][half * 2 + 0] + b0) * scale;
                float v1 = (acc[mt][nt][half * 2 + 1] + b1) * scale;
                if (ok) {
                    if (SPLIT_OUT) {
                        uint32_t h0, l0;
                        split2(v0, v1, h0, l0);
                        *(uint32_t*)(Ch + (size_t)tok * GK + n) = h0;
                        *(uint32_t*)(Cl + (size_t)tok * GK + n) = l0;
                    } else {
                        stg_cs_f2(C + (size_t)tok * GK + n, v0, v1);
                    }
                }
            }
        }
    }
}

// Merged Q/K/V projection + Vbar (z=3).
__global__ __launch_bounds__(256, 2)
void gemm_qkv_kernel(
    const __nv_bfloat16* __restrict__ Ah, const __nv_bfloat16* __restrict__ Al,
    const __nv_bfloat16* __restrict__ xbh, const __nv_bfloat16* __restrict__ xbl,
    const __nv_bfloat16* __restrict__ whb, const __nv_bfloat16* __restrict__ wlb,
    const float* __restrict__ bq, const float* __restrict__ bk, const float* __restrict__ bv,
    __nv_bfloat16* __restrict__ qh, __nv_bfloat16* __restrict__ ql,
    __nv_bfloat16* __restrict__ kh, __nv_bfloat16* __restrict__ kl,
    __nv_bfloat16* __restrict__ vh, __nv_bfloat16* __restrict__ vl,
    __nv_bfloat16* __restrict__ ch, __nv_bfloat16* __restrict__ cl)
{
    const int z = blockIdx.z;
    if (z == 3) {
        const int mi = blockIdx.y;
        const int nm = g_nm;
        if (mi * BM >= nm) return;
        const int valid = min(BM, nm - mi * BM);
        gemm_body<true, true>(xbh, xbl, whb + 2 * (size_t)NW_ELEM, wlb + 2 * (size_t)NW_ELEM,
                              bv, nullptr, ch, cl, 1.0f,
                              0, 0, g_cmap_m + mi * BM, valid, blockIdx.x * BN);
        return;
    }
    if ((int)blockIdx.y >= g_nu) return;
    const int tok_base = g_cmap_u[blockIdx.y];
    const __nv_bfloat16* Bh = whb + (size_t)z * NW_ELEM;
    const __nv_bfloat16* Bl = wlb + (size_t)z * NW_ELEM;
    const float* bias = (z == 0) ? bq : (z == 1) ? bk : bv;
    __nv_bfloat16* Ch = (z == 0) ? qh : (z == 1) ? kh : vh;
    __nv_bfloat16* Cl = (z == 0) ? ql : (z == 1) ? kl : vl;
    const float scale = (z == 0) ? SCALING : 1.0f;
    gemm_body<true, false>(Ah, Al, Bh, Bl, bias, nullptr, Ch, Cl, scale,
                           tok_base, C_DIM, nullptr, BM, blockIdx.x * BN);
}

// Output projection, unmasked columns; sel selects column half
// (sel=0 -> c < 128, sel=1 -> c >= 128) to pipeline with attention.
__global__ __launch_bounds__(256, 2)
void gemm_out_kernel(
    const __nv_bfloat16* __restrict__ Ah, const __nv_bfloat16* __restrict__ Al,
    const __nv_bfloat16* __restrict__ Bh, const __nv_bfloat16* __restrict__ Bl,
    const float* __restrict__ bias, float* __restrict__ C, int sel)
{
    if ((int)blockIdx.y >= g_nu) return;
    const int c = g_cmap_u[blockIdx.y];
    if ((c >= 128 ? 1 : 0) != sel) return;
    gemm_body<false, false>(Ah, Al, Bh, Bl, bias, C, nullptr, nullptr, 1.0f,
                            c, C_DIM, nullptr, BM, blockIdx.x * BN);
}

// Output projection, masked columns: one row (r=0) per masked column (gather).
__global__ __launch_bounds__(256, 2)
void gemm_outm_kernel(
    const __nv_bfloat16* __restrict__ Ah, const __nv_bfloat16* __restrict__ Al,
    const __nv_bfloat16* __restrict__ Bh, const __nv_bfloat16* __restrict__ Bl,
    const float* __restrict__ bias, float* __restrict__ C)
{
    const int mi = blockIdx.y;
    const int nm = g_nm;
    if (mi * BM >= nm) return;
    const int valid = min(BM, nm - mi * BM);
    gemm_body<false, true>(Ah, Al, Bh, Bl, bias, C, nullptr, nullptr, 1.0f,
                           0, 0, g_cmap_m + mi * BM, valid, blockIdx.x * BN);
}

// Broadcast masked-column output row r=0 to rows 1..127 (bit-exact copy).
__global__ __launch_bounds__(192) void bcast_out_kernel(
    const int* __restrict__ mask, float* __restrict__ out)
{
    const int c = blockIdx.x;
    if (mask[c] == 0) return;
    const int r = blockIdx.y + 1;
    const float4* src = (const float4*)(out + (size_t)c * E_DIM);
    float4* dst = (float4*)(out + ((size_t)r * C_DIM + c) * E_DIM);
    dst[threadIdx.x] = src[threadIdx.x];
}

// ---------------------------------------------------------------------------
// Tensor-core attention, UNMASKED columns only; c0 = column offset for
// half-grid launches (pipelining with the out-GEMM).
// ---------------------------------------------------------------------------
#define ATT_SMEM (98304 + 1024)
#define VH_OFF 65536
#define VL_OFF 81920

__global__ __launch_bounds__(256, 2) void attn_kernel(
    const __nv_bfloat16* __restrict__ Qh, const __nv_bfloat16* __restrict__ Ql,
    const __nv_bfloat16* __restrict__ Kh, const __nv_bfloat16* __restrict__ Kl,
    const __nv_bfloat16* __restrict__ Vh, const __nv_bfloat16* __restrict__ Vl,
    const int* __restrict__ mask, float* __restrict__ probs,
    __nv_bfloat16* __restrict__ Ch, __nv_bfloat16* __restrict__ Cl, int c0)
{
    extern __shared__ char smraw[];
    const uint32_t smb0 = smem_u32(smraw);
    const uint32_t smb = (smb0 + 1023) & ~1023u;

    const uint32_t QH = smb, QL = smb + 16384, KH = smb + 32768, KL = smb + 49152;
    const uint32_t VH = smb + VH_OFF, VL = smb + VL_OFF;

    const int c = blockIdx.x + c0, hh = blockIdx.y;
    if (mask[c] != 0) return;

    const int t = threadIdx.x, lane = t & 31, w = t >> 5;
    const int w16 = w * 16;
    const int r1 = w16 + (lane >> 2), r2 = r1 + 8;
    const int jb = (lane & 3) * 2;

#pragma unroll
    for (int p = 0; p < 4; p++) {
        int u = t + p * 256;
        int row = u >> 3, seg = u & 7;
        size_t g = ((size_t)row * C_DIM + c) * E_DIM + hh * 64 + seg * 8;
        uint32_t so = SMEM_SWZ(row * 128 + seg * 16);
        cp_async16(QH + so, Qh + g);
        cp_async16(QL + so, Ql + g);
        cp_async16(KH + so, Kh + g);
        cp_async16(KL + so, Kl + g);
        cp_async16(VH + so, Vh + g);
        cp_async16(VL + so, Vl + g);
    }
    cp_commit();
    cp_wait<0>();
    __syncthreads();

    const int a_row = lane & 15, a_k8 = (lane >> 4) * 8;
    const int b_row = (lane & 7) + ((lane >> 4) & 1) * 8, b_k8 = ((lane >> 3) & 1) * 8;

    float S[16][4];
#pragma unroll
    for (int nt = 0; nt < 16; nt++)
#pragma unroll
        for (int q = 0; q < 4; q++) S[nt][q] = 0.0f;

#pragma unroll
    for (int kk = 0; kk < 4; kk++) {
        uint32_t ao = SMEM_SWZ((w16 + a_row) * 128 + (kk * 16 + a_k8) * 2);
        uint32_t ah[4], al[4];
        ldmx4(ah, QH + ao);
        ldmx4(al, QL + ao);
#pragma unroll
        for (int nb = 0; nb < 8; nb++) {
            uint32_t bo = SMEM_SWZ((nb * 16 + b_row) * 128 + (kk * 16 + b_k8) * 2);
            uint32_t bh[4], bl[4];
            ldmx4(bh, KH + bo);
            ldmx4(bl, KL + bo);
            mma16816(S[nb * 2], ah, bh);
            mma16816(S[nb * 2], ah, bl);
            mma16816(S[nb * 2], al, bh);
            mma16816(S[nb * 2 + 1], ah, bh + 2);
            mma16816(S[nb * 2 + 1], ah, bl + 2);
            mma16816(S[nb * 2 + 1], al, bh + 2);
        }
    }

    float mx1 = -1e30f, mx2 = -1e30f;
#pragma unroll
    for (int nt = 0; nt < 16; nt++) {
        mx1 = fmaxf(mx1, fmaxf(S[nt][0], S[nt][1]));
        mx2 = fmaxf(mx2, fmaxf(S[nt][2], S[nt][3]));
    }
    mx1 = fmaxf(mx1, __shfl_xor_sync(0xFFFFFFFF, mx1, 1));
    mx1 = fmaxf(mx1, __shfl_xor_sync(0xFFFFFFFF, mx1, 2));
    mx2 = fmaxf(mx2, __shfl_xor_sync(0xFFFFFFFF, mx2, 1));
    mx2 = fmaxf(mx2, __shfl_xor_sync(0xFFFFFFFF, mx2, 2));

    float s1 = 0.0f, s2v = 0.0f;
#pragma unroll
    for (int nt = 0; nt < 16; nt++) {
        S[nt][0] = __expf(S[nt][0] - mx1); s1 += S[nt][0];
        S[nt][1] = __expf(S[nt][1] - mx1); s1 += S[nt][1];
        S[nt][2] = __expf(S[nt][2] - mx2); s2v += S[nt][2];
        S[nt][3] = __expf(S[nt][3] - mx2); s2v += S[nt][3];
    }
    s1 += __shfl_xor_sync(0xFFFFFFFF, s1, 1);
    s1 += __shfl_xor_sync(0xFFFFFFFF, s1, 2);
    s2v += __shfl_xor_sync(0xFFFFFFFF, s2v, 1);
    s2v += __shfl_xor_sync(0xFFFFFFFF, s2v, 2);
    const float inv1 = 1.0f / s1, inv2 = 1.0f / s2v;
#pragma unroll
    for (int nt = 0; nt < 16; nt++) {
        S[nt][0] *= inv1; S[nt][1] *= inv1;
        S[nt][2] *= inv2; S[nt][3] *= inv2;
    }

    {
        float* p1 = probs + ((size_t)hh * C_DIM + c) * 16384 + (size_t)r1 * 128 + jb;
        float* p2 = probs + ((size_t)hh * C_DIM + c) * 16384 + (size_t)r2 * 128 + jb;
#pragma unroll
        for (int nt = 0; nt < 16; nt++) {
            stg_cs_f2(p1 + nt * 8, S[nt][0], S[nt][1]);
            stg_cs_f2(p2 + nt * 8, S[nt][2], S[nt][3]);
        }
    }

    uint32_t ph[8][4], pl[8][4];
#pragma unroll
    for (int q = 0; q < 8; q++) {
        const int nt0 = 2 * q, nt1 = 2 * q + 1;
        split2(S[nt0][0], S[nt0][1], ph[q][0], pl[q][0]);
        split2(S[nt0][2], S[nt0][3], ph[q][1], pl[q][1]);
        split2(S[nt1][0], S[nt1][1], ph[q][2], pl[q][2]);
        split2(S[nt1][2], S[nt1][3], ph[q][3], pl[q][3]);
    }

    const int v_row = (lane & 7) + ((lane >> 3) & 1) * 8;
    const int v_half = (lane >> 4) * 16;

    float Cc[8][4];
#pragma unroll
    for (int nf = 0; nf < 8; nf++)
#pragma unroll
        for (int q = 0; q < 4; q++) Cc[nf][q] = 0.0f;

#pragma unroll
    for (int q = 0; q < 8; q++) {
#pragma unroll
        for (int df = 0; df < 4; df++) {
            uint32_t off = SMEM_SWZ((q * 16 + v_row) * 128 + df * 32 + v_half);
            uint32_t vh[4], vl[4];
            ldmx4t(vh, VH + off);
            ldmx4t(vl, VL + off);
            mma16816(Cc[df * 2], ph[q], vh);
            mma16816(Cc[df * 2], ph[q], vl);
            mma16816(Cc[df * 2], pl[q], vh);
            mma16816(Cc[df * 2 + 1], ph[q], vh + 2);
            mma16816(Cc[df * 2 + 1], ph[q], vl + 2);
            mma16816(Cc[df * 2 + 1], pl[q], vh + 2);
        }
    }

#pragma unroll
    for (int nf = 0; nf < 8; nf++) {
        const int d = nf * 8 + jb;
        size_t o1 = ((size_t)r1 * C_DIM + c) * E_DIM + hh * 64 + d;
        size_t o2 = ((size_t)r2 * C_DIM + c) * E_DIM + hh * 64 + d;
        uint32_t h0, l0, h1, l1;
        split2(Cc[nf][0], Cc[nf][1], h0, l0);
        split2(Cc[nf][2], Cc[nf][3], h1, l1);
        *(uint32_t*)(Ch + o1) = h0;
        *(uint32_t*)(Cl + o1) = l0;
        *(uint32_t*)(Ch + o2) = h1;
        *(uint32_t*)(Cl + o2) = l1;
    }
}

// ---------------------------------------------------------------------------
extern "C" void kernel_launch(void* const* d_in, const int* in_sizes, int n_in,
                              void* d_out, int out_size)
{
    const float* x  = (const float*)d_in[0];
    const int*   mask = (const int*)d_in[1];
    const float* wq = (const float*)d_in[2];
    const float* bq = (const float*)d_in[3];
    const float* wk = (const float*)d_in[4];
    const float* bk = (const float*)d_in[5];
    const float* wv = (const float*)d_in[6];
    const float* bv = (const float*)d_in[7];
    const float* wo = (const float*)d_in[8];
    const float* bo = (const float*)d_in[9];

    float* out   = (float*)d_out;
    float* probs = (float*)d_out + (size_t)M_TOK * E_DIM;

    __nv_bfloat16 *xh, *xl, *qh, *ql, *kh, *kl, *vh, *vl, *ch, *cl, *wh, *wl, *xbh, *xbl;
    cudaGetSymbolAddress((void**)&xh, g_xh);
    cudaGetSymbolAddress((void**)&xl, g_xl);
    cudaGetSymbolAddress((void**)&qh, g_qh);
    cudaGetSymbolAddress((void**)&ql, g_ql);
    cudaGetSymbolAddress((void**)&kh, g_kh);
    cudaGetSymbolAddress((void**)&kl, g_kl);
    cudaGetSymbolAddress((void**)&vh, g_vh);
    cudaGetSymbolAddress((void**)&vl, g_vl);
    cudaGetSymbolAddress((void**)&ch, g_ch);
    cudaGetSymbolAddress((void**)&cl, g_cl);
    cudaGetSymbolAddress((void**)&wh, g_wh);
    cudaGetSymbolAddress((void**)&wl, g_wl);
    cudaGetSymbolAddress((void**)&xbh, g_xbh);
    cudaGetSymbolAddress((void**)&xbl, g_xbl);

    static cudaStream_t s2 = nullptr;
    static cudaEvent_t evF = nullptr, evX = nullptr, evQ = nullptr,
                       evA1 = nullptr, evB = nullptr;
    static bool attr_set = false;
    if (!attr_set) {
        cudaFuncSetAttribute(attn_kernel, cudaFuncAttributeMaxDynamicSharedMemorySize,
                             ATT_SMEM);
        cudaFuncSetAttribute(gemm_qkv_kernel, cudaFuncAttributeMaxDynamicSharedMemorySize,
                             GEMM_SMEM);
        cudaFuncSetAttribute(gemm_out_kernel, cudaFuncAttributeMaxDynamicSharedMemorySize,
                             GEMM_SMEM);
        cudaFuncSetAttribute(gemm_outm_kernel, cudaFuncAttributeMaxDynamicSharedMemorySize,
                             GEMM_SMEM);
        cudaStreamCreateWithFlags(&s2, cudaStreamNonBlocking);
        cudaEventCreateWithFlags(&evF, cudaEventDisableTiming);
        cudaEventCreateWithFlags(&evX, cudaEventDisableTiming);
        cudaEventCreateWithFlags(&evQ, cudaEventDisableTiming);
        cudaEventCreateWithFlags(&evA1, cudaEventDisableTiming);
        cudaEventCreateWithFlags(&evB, cudaEventDisableTiming);
        attr_set = true;
    }

    const size_t wo_off = 3 * (size_t)NW_ELEM;

    // fork stream B: xbar (feeds QKV z=3), then masked probs fill
    cudaEventRecord(evF, 0);
    cudaStreamWaitEvent(s2, evF, 0);
    xbar_kernel<<<C_DIM, 256, 0, s2>>>(x, mask, xbh, xbl);
    cudaEventRecord(evX, s2);
    probs_fill_kernel<<<dim3(C_DIM, H_DIM), 256, 0, s2>>>(mask, probs);

    // main chain
    prep_mask_kernel<<<1, 256>>>(mask);
    split_all_kernel<<<4224, 256>>>(x, mask, wq, wk, wv, wo, xh, xl, wh, wl);
    cudaStreamWaitEvent(0, evX, 0);

    dim3 gqkv(E_DIM / BN, C_DIM, 4);        // z=0..2 QKV (exit beyond nu), z=3 Vbar
    gemm_qkv_kernel<<<gqkv, 256, GEMM_SMEM>>>(xh, xl, xbh, xbl, wh, wl, bq, bk, bv,
                                              qh, ql, kh, kl, vh, vl, ch, cl);
    cudaEventRecord(evQ, 0);

    // stream B: masked out row0 + broadcast (depends on Vbar ctx from QKV)
    cudaStreamWaitEvent(s2, evQ, 0);
    gemm_outm_kernel<<<dim3(E_DIM / BN, 2), 256, GEMM_SMEM, s2>>>(
        ch, cl, wh + wo_off, wl + wo_off, bo, out);
    bcast_out_kernel<<<dim3(C_DIM, R_DIM - 1), 192, 0, s2>>>(mask, out);

    // attention in two column halves; out-GEMM for the first half overlaps
    // attention for the second half.
    dim3 ga(C_DIM / 2, H_DIM);
    attn_kernel<<<ga, 256, ATT_SMEM>>>(qh, ql, kh, kl, vh, vl, mask, probs, ch, cl, 0);
    cudaEventRecord(evA1, 0);
    attn_kernel<<<ga, 256, ATT_SMEM>>>(qh, ql, kh, kl, vh, vl, mask, probs, ch, cl, 128);

    cudaStreamWaitEvent(s2, evA1, 0);
    dim3 gout(E_DIM / BN, C_DIM);
    gemm_out_kernel<<<gout, 256, GEMM_SMEM, s2>>>(ch, cl, wh + wo_off, wl + wo_off,
                                                  bo, out, 0);
    cudaEventRecord(evB, s2);

    // main: out for second-half columns, then join stream B
    gemm_out_kernel<<<gout, 256, GEMM_SMEM>>>(ch, cl, wh + wo_off, wl + wo_off,
                                              bo, out, 1);
    cudaStreamWaitEvent(0, evB, 0);
}

// round 17
// speedup vs baseline: 1.0183x; 1.0183x over previous
#include <cuda_runtime.h>
#include <cuda_bf16.h>
#include <cstdint>
#include <math.h>

// Problem constants
#define R_DIM 128
#define C_DIM 256
#define E_DIM 768
#define H_DIM 12
#define D_DIM 64
#define M_TOK (R_DIM * C_DIM)          // 32768
#define SCALING 0.125f
#define NW_ELEM (E_DIM * E_DIM)

// bf16 hi/lo scratch (device globals; no allocation)
__device__ __align__(128) __nv_bfloat16 g_xh[M_TOK * E_DIM];
__device__ __align__(128) __nv_bfloat16 g_xl[M_TOK * E_DIM];
__device__ __align__(128) __nv_bfloat16 g_qh[M_TOK * E_DIM];
__device__ __align__(128) __nv_bfloat16 g_ql[M_TOK * E_DIM];
__device__ __align__(128) __nv_bfloat16 g_kh[M_TOK * E_DIM];
__device__ __align__(128) __nv_bfloat16 g_kl[M_TOK * E_DIM];
__device__ __align__(128) __nv_bfloat16 g_vh[M_TOK * E_DIM];
__device__ __align__(128) __nv_bfloat16 g_vl[M_TOK * E_DIM];
__device__ __align__(128) __nv_bfloat16 g_ch[M_TOK * E_DIM];
__device__ __align__(128) __nv_bfloat16 g_cl[M_TOK * E_DIM];
__device__ __align__(128) __nv_bfloat16 g_wh[4][NW_ELEM];
__device__ __align__(128) __nv_bfloat16 g_wl[4][NW_ELEM];
// column-mean of x for masked columns (bf16 split), indexed by column c
__device__ __align__(128) __nv_bfloat16 g_xbh[C_DIM * E_DIM];
__device__ __align__(128) __nv_bfloat16 g_xbl[C_DIM * E_DIM];

// mask compaction (device-side; deterministic prefix scan)
__device__ int g_cmap_u[256];
__device__ int g_cmap_m[256];
__device__ int g_nu;
__device__ int g_nm;

// ---------------------------------------------------------------------------
// Helpers
// ---------------------------------------------------------------------------
__device__ __forceinline__ uint32_t smem_u32(const void* p) {
    uint32_t a;
    asm("{ .reg .u64 t; cvta.to.shared.u64 t, %1; cvt.u32.u64 %0, t; }" : "=r"(a) : "l"(p));
    return a;
}
__device__ __forceinline__ void cp_async16(uint32_t s, const void* g) {
    size_t ga = __cvta_generic_to_global(g);
    asm volatile("cp.async.cg.shared.global [%0], [%1], 16;" :: "r"(s), "l"(ga));
}
__device__ __forceinline__ void cp_commit() { asm volatile("cp.async.commit_group;" ::: "memory"); }
template <int N> __device__ __forceinline__ void cp_wait() {
    asm volatile("cp.async.wait_group %0;" :: "n"(N) : "memory");
}
__device__ __forceinline__ void ldmx4(uint32_t* r, uint32_t addr) {
    asm volatile("ldmatrix.sync.aligned.m8n8.x4.shared.b16 {%0,%1,%2,%3}, [%4];"
        : "=r"(r[0]), "=r"(r[1]), "=r"(r[2]), "=r"(r[3]) : "r"(addr));
}
__device__ __forceinline__ void ldmx4t(uint32_t* r, uint32_t addr) {
    asm volatile("ldmatrix.sync.aligned.m8n8.x4.trans.shared.b16 {%0,%1,%2,%3}, [%4];"
        : "=r"(r[0]), "=r"(r[1]), "=r"(r[2]), "=r"(r[3]) : "r"(addr));
}
__device__ __forceinline__ void mma16816(float* c, const uint32_t* a, const uint32_t* b) {
    asm volatile("mma.sync.aligned.m16n8k16.row.col.f32.bf16.bf16.f32 "
        "{%0,%1,%2,%3}, {%4,%5,%6,%7}, {%8,%9}, {%0,%1,%2,%3};"
        : "+f"(c[0]), "+f"(c[1]), "+f"(c[2]), "+f"(c[3])
        : "r"(a[0]), "r"(a[1]), "r"(a[2]), "r"(a[3]), "r"(b[0]), "r"(b[1]));
}
__device__ __forceinline__ void split2(float f0, float f1, uint32_t& hi, uint32_t& lo) {
    __nv_bfloat16 h0 = __float2bfloat16(f0);
    __nv_bfloat16 h1 = __float2bfloat16(f1);
    __nv_bfloat16 l0 = __float2bfloat16(f0 - __bfloat162float(h0));
    __nv_bfloat16 l1 = __float2bfloat16(f1 - __bfloat162float(h1));
    __nv_bfloat162 hp = { h0, h1 }, lp = { l0, l1 };
    hi = *(uint32_t*)&hp;
    lo = *(uint32_t*)&lp;
}
__device__ __forceinline__ void stg_cs_f2(float* p, float a, float b) {
    asm volatile("st.global.cs.v2.f32 [%0], {%1, %2};" :: "l"(p), "f"(a), "f"(b));
}
__device__ __forceinline__ void stg_cs_f4(float* p, float a, float b, float c, float d) {
    asm volatile("st.global.cs.v4.f32 [%0], {%1, %2, %3, %4};"
        :: "l"(p), "f"(a), "f"(b), "f"(c), "f"(d));
}

#define SMEM_SWZ(o) ((o) ^ (((o) >> 3) & 0x70))

// ---------------------------------------------------------------------------
// Mask prep: deterministic Hillis-Steele scan, 1 block x 256 threads.
// ---------------------------------------------------------------------------
__global__ void prep_mask_kernel(const int* __restrict__ mask) {
    __shared__ int pu[256], pm[256];
    const int c = threadIdx.x;
    const int mu = (mask[c] == 0) ? 1 : 0;
    pu[c] = mu;
    pm[c] = 1 - mu;
    __syncthreads();
    for (int off = 1; off < 256; off <<= 1) {
        int vu = (c >= off) ? pu[c - off] : 0;
        int vm = (c >= off) ? pm[c - off] : 0;
        __syncthreads();
        pu[c] += vu;
        pm[c] += vm;
        __syncthreads();
    }
    if (mu) g_cmap_u[pu[c] - 1] = c;
    else    g_cmap_m[pm[c] - 1] = c;
    if (c == 255) { g_nu = pu[255]; g_nm = pm[255]; }
}

// ---------------------------------------------------------------------------
// Masked probs fill: probs[h][c][:][:] = 1/128 exactly (stream B).
// ---------------------------------------------------------------------------
__global__ __launch_bounds__(256) void probs_fill_kernel(
    const int* __restrict__ mask, float* __restrict__ probs)
{
    const int c = blockIdx.x;
    if (mask[c] == 0) return;
    const int hh = blockIdx.y;
    const float u = 0.0078125f;
    float* base = probs + ((size_t)hh * C_DIM + c) * 16384;
#pragma unroll
    for (int i = 0; i < 16; i++)
        stg_cs_f4(base + (threadIdx.x + i * 256) * 4, u, u, u, u);
}

// ---------------------------------------------------------------------------
// xbar: column mean of x over rows, for masked columns only -> bf16 split.
// ---------------------------------------------------------------------------
__global__ __launch_bounds__(256) void xbar_kernel(
    const float* __restrict__ x, const int* __restrict__ mask,
    __nv_bfloat16* __restrict__ xbh, __nv_bfloat16* __restrict__ xbl)
{
    const int c = blockIdx.x;
    if (mask[c] == 0) return;
    const int t = threadIdx.x;
#pragma unroll
    for (int u = 0; u < 3; u++) {
        const int d = t + u * 256;
        float s = 0.0f;
        for (int r = 0; r < R_DIM; r++)
            s += x[((size_t)r * C_DIM + c) * E_DIM + d];
        s *= 0.0078125f;
        __nv_bfloat16 h = __float2bfloat16(s);
        __nv_bfloat16 l = __float2bfloat16(s - __bfloat162float(h));
        xbh[(size_t)c * E_DIM + d] = h;
        xbl[(size_t)c * E_DIM + d] = l;
    }
}

// ---------------------------------------------------------------------------
// Merged split: x (unmasked-column tokens only) + 4 weights, grid-stride.
// ---------------------------------------------------------------------------
#define NX_ELEM (M_TOK * E_DIM)
#define NX4 (NX_ELEM / 4)
#define NW4 (NW_ELEM / 4)
#define NTOT4 (NX4 + 4 * NW4)
#define TOK_F4 (E_DIM / 4)              // 192 float4 per token

__device__ __forceinline__ void split_store(const float* __restrict__ in,
                                            __nv_bfloat16* __restrict__ hi,
                                            __nv_bfloat16* __restrict__ lo, int i)
{
    float4 v = ((const float4*)in)[i];
    __nv_bfloat16 h[4], l[4];
    h[0] = __float2bfloat16(v.x); l[0] = __float2bfloat16(v.x - __bfloat162float(h[0]));
    h[1] = __float2bfloat16(v.y); l[1] = __float2bfloat16(v.y - __bfloat162float(h[1]));
    h[2] = __float2bfloat16(v.z); l[2] = __float2bfloat16(v.z - __bfloat162float(h[2]));
    h[3] = __float2bfloat16(v.w); l[3] = __float2bfloat16(v.w - __bfloat162float(h[3]));
    ((uint2*)hi)[i] = *(uint2*)h;
    ((uint2*)lo)[i] = *(uint2*)l;
}

__global__ __launch_bounds__(256) void split_all_kernel(
    const float* __restrict__ x, const int* __restrict__ mask,
    const float* __restrict__ w0, const float* __restrict__ w1,
    const float* __restrict__ w2, const float* __restrict__ w3,
    __nv_bfloat16* __restrict__ xh, __nv_bfloat16* __restrict__ xl,
    __nv_bfloat16* __restrict__ whb, __nv_bfloat16* __restrict__ wlb)
{
    __shared__ unsigned char msk[256];
    if (threadIdx.x < 256) msk[threadIdx.x] = (mask[threadIdx.x] != 0);
    __syncthreads();

    const float* wsrc[4] = { w0, w1, w2, w3 };
    for (int i = blockIdx.x * blockDim.x + threadIdx.x; i < NTOT4; i += gridDim.x * blockDim.x) {
        if (i < NX4) {
            const int tok = i / TOK_F4;
            if (msk[tok & 255]) continue;
            split_store(x, xh, xl, i);
        } else {
            int j = i - NX4;
            int b = j / NW4, r = j - b * NW4;
            split_store(wsrc[b], whb + (size_t)b * NW_ELEM, wlb + (size_t)b * NW_ELEM, r);
        }
    }
}

// ---------------------------------------------------------------------------
// mma.sync GEMM body
// ---------------------------------------------------------------------------
#define GK 768
#define BM 128
#define BN 64
#define BK 64
#define NCHUNK (GK / BK)                 // 12
#define ABUF_BYTES (128 * 128)           // 16384
#define BBUF_BYTES (64 * 128)            // 8192
#define STAGE_BYTES (2 * ABUF_BYTES + 2 * BBUF_BYTES)   // 49152
#define GEMM_SMEM (2 * STAGE_BYTES + 1024)

template <bool GATHER>
__device__ __forceinline__ void load_chunk(
    uint32_t stage,
    const __nv_bfloat16* __restrict__ Ah, const __nv_bfloat16* __restrict__ Al,
    const __nv_bfloat16* __restrict__ Bh, const __nv_bfloat16* __restrict__ Bl,
    int tok_base, int tok_stride, const int* __restrict__ gather,
    int n0, int kc, int t)
{
#pragma unroll
    for (int p = 0; p < 4; p++) {
        int u = t + p * 256;
        int row = u >> 3, seg = u & 7;
        int tok = GATHER ? gather[row] : (tok_base + row * tok_stride);
        size_t go = (size_t)tok * GK + kc + seg * 8;
        uint32_t so = SMEM_SWZ(row * 128 + seg * 16);
        cp_async16(stage + so, Ah + go);
        cp_async16(stage + ABUF_BYTES + so, Al + go);
    }
#pragma unroll
    for (int p = 0; p < 2; p++) {
        int u = t + p * 256;
        int row = u >> 3, seg = u & 7;
        size_t go = (size_t)(n0 + row) * GK + kc + seg * 8;
        uint32_t so = SMEM_SWZ(row * 128 + seg * 16);
        cp_async16(stage + 2 * ABUF_BYTES + so, Bh + go);
        cp_async16(stage + 2 * ABUF_BYTES + BBUF_BYTES + so, Bl + go);
    }
}

template <bool SPLIT_OUT, bool GATHER>
__device__ __forceinline__ void gemm_body(
    const __nv_bfloat16* __restrict__ Ah, const __nv_bfloat16* __restrict__ Al,
    const __nv_bfloat16* __restrict__ Bh, const __nv_bfloat16* __restrict__ Bl,
    const float* __restrict__ bias, float* __restrict__ C,
    __nv_bfloat16* __restrict__ Ch, __nv_bfloat16* __restrict__ Cl,
    float scale, int tok_base, int tok_stride,
    const int* __restrict__ gather, int valid, int n0)
{
    extern __shared__ char smbuf[];
    const uint32_t tiles = (smem_u32(smbuf) + 1023) & ~1023u;
    const int t = threadIdx.x;
    const int lane = t & 31, wid = t >> 5;
    const int wm = wid >> 1, wn = wid & 1;

    const uint32_t stg[2] = { tiles, tiles + STAGE_BYTES };

    const int a_row = lane & 15;
    const int a_k8 = (lane >> 4) * 8;
    const int b_row = (lane & 7) + ((lane >> 4) & 1) * 8;
    const int b_k8 = ((lane >> 3) & 1) * 8;

    float acc[2][4][4];
#pragma unroll
    for (int mt = 0; mt < 2; mt++)
#pragma unroll
        for (int nt = 0; nt < 4; nt++)
#pragma unroll
            for (int q = 0; q < 4; q++) acc[mt][nt][q] = 0.0f;

    load_chunk<GATHER>(stg[0], Ah, Al, Bh, Bl, tok_base, tok_stride, gather, n0, 0, t);
    cp_commit();

    for (int c = 0; c < NCHUNK; c++) {
        const int s = c & 1;
        cp_wait<0>();
        __syncthreads();
        if (c + 1 < NCHUNK) {
            load_chunk<GATHER>(stg[s ^ 1], Ah, Al, Bh, Bl, tok_base, tok_stride, gather,
                               n0, (c + 1) * BK, t);
            cp_commit();
        }

        const uint32_t Abase = stg[s];
        const uint32_t Bbase = stg[s] + 2 * ABUF_BYTES;
#pragma unroll
        for (int kk = 0; kk < 4; kk++) {
            uint32_t ah[2][4], al[2][4];
#pragma unroll
            for (int mt = 0; mt < 2; mt++) {
                uint32_t off = (uint32_t)(wm * 32 + mt * 16 + a_row) * 128
                             + (kk * 16 + a_k8) * 2;
                uint32_t sw = SMEM_SWZ(off);
                ldmx4(ah[mt], Abase + sw);
                ldmx4(al[mt], Abase + ABUF_BYTES + sw);
            }
            uint32_t bh[2][4], bl[2][4];
#pragma unroll
            for (int nb = 0; nb < 2; nb++) {
                uint32_t off = (uint32_t)(wn * 32 + nb * 16 + b_row) * 128
                             + (kk * 16 + b_k8) * 2;
                uint32_t sw = SMEM_SWZ(off);
                ldmx4(bh[nb], Bbase + sw);
                ldmx4(bl[nb], Bbase + BBUF_BYTES + sw);
            }
#pragma unroll
            for (int mt = 0; mt < 2; mt++)
#pragma unroll
                for (int nt = 0; nt < 4; nt++) {
                    const uint32_t* fh = &bh[nt >> 1][(nt & 1) * 2];
                    const uint32_t* fl = &bl[nt >> 1][(nt & 1) * 2];
                    mma16816(acc[mt][nt], ah[mt], fh);
                    mma16816(acc[mt][nt], ah[mt], fl);
                    mma16816(acc[mt][nt], al[mt], fh);
                }
        }
    }

    // epilogue
#pragma unroll
    for (int mt = 0; mt < 2; mt++) {
        const int mrow = wm * 32 + mt * 16 + (lane >> 2);
#pragma unroll
        for (int half = 0; half < 2; half++) {
            const int rr = mrow + half * 8;
            const int tok = GATHER ? gather[rr] : (tok_base + rr * tok_stride);
            const bool ok = !GATHER || (rr < valid);
#pragma unroll
            for (int nt = 0; nt < 4; nt++) {
                const int n = n0 + wn * 32 + nt * 8 + (lane & 3) * 2;
                const float b0 = bias[n], b1 = bias[n + 1];
                float v0 = (acc[mt][nt][half * 2 + 0] + b0) * scale;
                float v1 = (acc[mt][nt][half * 2 + 1] + b1) * scale;
                if (ok) {
                    if (SPLIT_OUT) {
                        uint32_t h0, l0;
                        split2(v0, v1, h0, l0);
                        *(uint32_t*)(Ch + (size_t)tok * GK + n) = h0;
                        *(uint32_t*)(Cl + (size_t)tok * GK + n) = l0;
                    } else {
                        stg_cs_f2(C + (size_t)tok * GK + n, v0, v1);
                    }
                }
            }
        }
    }
}

// Merged Q/K/V projection + Vbar (z=3).
__global__ __launch_bounds__(256, 2)
void gemm_qkv_kernel(
    const __nv_bfloat16* __restrict__ Ah, const __nv_bfloat16* __restrict__ Al,
    const __nv_bfloat16* __restrict__ xbh, const __nv_bfloat16* __restrict__ xbl,
    const __nv_bfloat16* __restrict__ whb, const __nv_bfloat16* __restrict__ wlb,
    const float* __restrict__ bq, const float* __restrict__ bk, const float* __restrict__ bv,
    __nv_bfloat16* __restrict__ qh, __nv_bfloat16* __restrict__ ql,
    __nv_bfloat16* __restrict__ kh, __nv_bfloat16* __restrict__ kl,
    __nv_bfloat16* __restrict__ vh, __nv_bfloat16* __restrict__ vl,
    __nv_bfloat16* __restrict__ ch, __nv_bfloat16* __restrict__ cl)
{
    const int z = blockIdx.z;
    if (z == 3) {
        const int mi = blockIdx.y;
        const int nm = g_nm;
        if (mi * BM >= nm) return;
        const int valid = min(BM, nm - mi * BM);
        gemm_body<true, true>(xbh, xbl, whb + 2 * (size_t)NW_ELEM, wlb + 2 * (size_t)NW_ELEM,
                              bv, nullptr, ch, cl, 1.0f,
                              0, 0, g_cmap_m + mi * BM, valid, blockIdx.x * BN);
        return;
    }
    if ((int)blockIdx.y >= g_nu) return;
    const int tok_base = g_cmap_u[blockIdx.y];
    const __nv_bfloat16* Bh = whb + (size_t)z * NW_ELEM;
    const __nv_bfloat16* Bl = wlb + (size_t)z * NW_ELEM;
    const float* bias = (z == 0) ? bq : (z == 1) ? bk : bv;
    __nv_bfloat16* Ch = (z == 0) ? qh : (z == 1) ? kh : vh;
    __nv_bfloat16* Cl = (z == 0) ? ql : (z == 1) ? kl : vl;
    const float scale = (z == 0) ? SCALING : 1.0f;
    gemm_body<true, false>(Ah, Al, Bh, Bl, bias, nullptr, Ch, Cl, scale,
                           tok_base, C_DIM, nullptr, BM, blockIdx.x * BN);
}

// Output projection, unmasked columns only.
__global__ __launch_bounds__(256, 2)
void gemm_out_kernel(
    const __nv_bfloat16* __restrict__ Ah, const __nv_bfloat16* __restrict__ Al,
    const __nv_bfloat16* __restrict__ Bh, const __nv_bfloat16* __restrict__ Bl,
    const float* __restrict__ bias, float* __restrict__ C)
{
    if ((int)blockIdx.y >= g_nu) return;
    gemm_body<false, false>(Ah, Al, Bh, Bl, bias, C, nullptr, nullptr, 1.0f,
                            g_cmap_u[blockIdx.y], C_DIM, nullptr, BM, blockIdx.x * BN);
}

// Output projection, masked columns: one row (r=0) per masked column (gather).
__global__ __launch_bounds__(256, 2)
void gemm_outm_kernel(
    const __nv_bfloat16* __restrict__ Ah, const __nv_bfloat16* __restrict__ Al,
    const __nv_bfloat16* __restrict__ Bh, const __nv_bfloat16* __restrict__ Bl,
    const float* __restrict__ bias, float* __restrict__ C)
{
    const int mi = blockIdx.y;
    const int nm = g_nm;
    if (mi * BM >= nm) return;
    const int valid = min(BM, nm - mi * BM);
    gemm_body<false, true>(Ah, Al, Bh, Bl, bias, C, nullptr, nullptr, 1.0f,
                           0, 0, g_cmap_m + mi * BM, valid, blockIdx.x * BN);
}

// Broadcast masked-column output row r=0 to rows 1..127 (bit-exact copy).
__global__ __launch_bounds__(192) void bcast_out_kernel(
    const int* __restrict__ mask, float* __restrict__ out)
{
    const int c = blockIdx.x;
    if (mask[c] == 0) return;
    const int r = blockIdx.y + 1;
    const float4* src = (const float4*)(out + (size_t)c * E_DIM);
    float4* dst = (float4*)(out + ((size_t)r * C_DIM + c) * E_DIM);
    dst[threadIdx.x] = src[threadIdx.x];
}

// ---------------------------------------------------------------------------
// Tensor-core attention, UNMASKED columns only (masked handled elsewhere).
// ---------------------------------------------------------------------------
#define ATT_SMEM (98304 + 1024)
#define VH_OFF 65536
#define VL_OFF 81920

__global__ __launch_bounds__(256, 2) void attn_kernel(
    const __nv_bfloat16* __restrict__ Qh, const __nv_bfloat16* __restrict__ Ql,
    const __nv_bfloat16* __restrict__ Kh, const __nv_bfloat16* __restrict__ Kl,
    const __nv_bfloat16* __restrict__ Vh, const __nv_bfloat16* __restrict__ Vl,
    const int* __restrict__ mask, float* __restrict__ probs,
    __nv_bfloat16* __restrict__ Ch, __nv_bfloat16* __restrict__ Cl)
{
    extern __shared__ char smraw[];
    const uint32_t smb0 = smem_u32(smraw);
    const uint32_t smb = (smb0 + 1023) & ~1023u;

    const uint32_t QH = smb, QL = smb + 16384, KH = smb + 32768, KL = smb + 49152;
    const uint32_t VH = smb + VH_OFF, VL = smb + VL_OFF;

    const int c = blockIdx.x, hh = blockIdx.y;
    if (mask[c] != 0) return;   // masked handled by probs_fill / Vbar / outm / bcast

    const int t = threadIdx.x, lane = t & 31, w = t >> 5;
    const int w16 = w * 16;
    const int r1 = w16 + (lane >> 2), r2 = r1 + 8;
    const int jb = (lane & 3) * 2;

#pragma unroll
    for (int p = 0; p < 4; p++) {
        int u = t + p * 256;
        int row = u >> 3, seg = u & 7;
        size_t g = ((size_t)row * C_DIM + c) * E_DIM + hh * 64 + seg * 8;
        uint32_t so = SMEM_SWZ(row * 128 + seg * 16);
        cp_async16(QH + so, Qh + g);
        cp_async16(QL + so, Ql + g);
        cp_async16(KH + so, Kh + g);
        cp_async16(KL + so, Kl + g);
        cp_async16(VH + so, Vh + g);
        cp_async16(VL + so, Vl + g);
    }
    cp_commit();
    cp_wait<0>();
    __syncthreads();

    const int a_row = lane & 15, a_k8 = (lane >> 4) * 8;
    const int b_row = (lane & 7) + ((lane >> 4) & 1) * 8, b_k8 = ((lane >> 3) & 1) * 8;

    float S[16][4];
#pragma unroll
    for (int nt = 0; nt < 16; nt++)
#pragma unroll
        for (int q = 0; q < 4; q++) S[nt][q] = 0.0f;

#pragma unroll
    for (int kk = 0; kk < 4; kk++) {
        uint32_t ao = SMEM_SWZ((w16 + a_row) * 128 + (kk * 16 + a_k8) * 2);
        uint32_t ah[4], al[4];
        ldmx4(ah, QH + ao);
        ldmx4(al, QL + ao);
#pragma unroll
        for (int nb = 0; nb < 8; nb++) {
            uint32_t bo = SMEM_SWZ((nb * 16 + b_row) * 128 + (kk * 16 + b_k8) * 2);
            uint32_t bh[4], bl[4];
            ldmx4(bh, KH + bo);
            ldmx4(bl, KL + bo);
            mma16816(S[nb * 2], ah, bh);
            mma16816(S[nb * 2], ah, bl);
            mma16816(S[nb * 2], al, bh);
            mma16816(S[nb * 2 + 1], ah, bh + 2);
            mma16816(S[nb * 2 + 1], ah, bl + 2);
            mma16816(S[nb * 2 + 1], al, bh + 2);
        }
    }

    float mx1 = -1e30f, mx2 = -1e30f;
#pragma unroll
    for (int nt = 0; nt < 16; nt++) {
        mx1 = fmaxf(mx1, fmaxf(S[nt][0], S[nt][1]));
        mx2 = fmaxf(mx2, fmaxf(S[nt][2], S[nt][3]));
    }
    mx1 = fmaxf(mx1, __shfl_xor_sync(0xFFFFFFFF, mx1, 1));
    mx1 = fmaxf(mx1, __shfl_xor_sync(0xFFFFFFFF, mx1, 2));
    mx2 = fmaxf(mx2, __shfl_xor_sync(0xFFFFFFFF, mx2, 1));
    mx2 = fmaxf(mx2, __shfl_xor_sync(0xFFFFFFFF, mx2, 2));

    float s1 = 0.0f, s2v = 0.0f;
#pragma unroll
    for (int nt = 0; nt < 16; nt++) {
        S[nt][0] = __expf(S[nt][0] - mx1); s1 += S[nt][0];
        S[nt][1] = __expf(S[nt][1] - mx1); s1 += S[nt][1];
        S[nt][2] = __expf(S[nt][2] - mx2); s2v += S[nt][2];
        S[nt][3] = __expf(S[nt][3] - mx2); s2v += S[nt][3];
    }
    s1 += __shfl_xor_sync(0xFFFFFFFF, s1, 1);
    s1 += __shfl_xor_sync(0xFFFFFFFF, s1, 2);
    s2v += __shfl_xor_sync(0xFFFFFFFF, s2v, 1);
    s2v += __shfl_xor_sync(0xFFFFFFFF, s2v, 2);
    const float inv1 = 1.0f / s1, inv2 = 1.0f / s2v;
#pragma unroll
    for (int nt = 0; nt < 16; nt++) {
        S[nt][0] *= inv1; S[nt][1] *= inv1;
        S[nt][2] *= inv2; S[nt][3] *= inv2;
    }

    {
        float* p1 = probs + ((size_t)hh * C_DIM + c) * 16384 + (size_t)r1 * 128 + jb;
        float* p2 = probs + ((size_t)hh * C_DIM + c) * 16384 + (size_t)r2 * 128 + jb;
#pragma unroll
        for (int nt = 0; nt < 16; nt++) {
            stg_cs_f2(p1 + nt * 8, S[nt][0], S[nt][1]);
            stg_cs_f2(p2 + nt * 8, S[nt][2], S[nt][3]);
        }
    }

    uint32_t ph[8][4], pl[8][4];
#pragma unroll
    for (int q = 0; q < 8; q++) {
        const int nt0 = 2 * q, nt1 = 2 * q + 1;
        split2(S[nt0][0], S[nt0][1], ph[q][0], pl[q][0]);
        split2(S[nt0][2], S[nt0][3], ph[q][1], pl[q][1]);
        split2(S[nt1][0], S[nt1][1], ph[q][2], pl[q][2]);
        split2(S[nt1][2], S[nt1][3], ph[q][3], pl[q][3]);
    }

    const int v_row = (lane & 7) + ((lane >> 3) & 1) * 8;
    const int v_half = (lane >> 4) * 16;

    float Cc[8][4];
#pragma unroll
    for (int nf = 0; nf < 8; nf++)
#pragma unroll
        for (int q = 0; q < 4; q++) Cc[nf][q] = 0.0f;

#pragma unroll
    for (int q = 0; q < 8; q++) {
#pragma unroll
        for (int df = 0; df < 4; df++) {
            uint32_t off = SMEM_SWZ((q * 16 + v_row) * 128 + df * 32 + v_half);
            uint32_t vh[4], vl[4];
            ldmx4t(vh, VH + off);
            ldmx4t(vl, VL + off);
            mma16816(Cc[df * 2], ph[q], vh);
            mma16816(Cc[df * 2], ph[q], vl);
            mma16816(Cc[df * 2], pl[q], vh);
            mma16816(Cc[df * 2 + 1], ph[q], vh + 2);
            mma16816(Cc[df * 2 + 1], ph[q], vl + 2);
            mma16816(Cc[df * 2 + 1], pl[q], vh + 2);
        }
    }

#pragma unroll
    for (int nf = 0; nf < 8; nf++) {
        const int d = nf * 8 + jb;
        size_t o1 = ((size_t)r1 * C_DIM + c) * E_DIM + hh * 64 + d;
        size_t o2 = ((size_t)r2 * C_DIM + c) * E_DIM + hh * 64 + d;
        uint32_t h0, l0, h1, l1;
        split2(Cc[nf][0], Cc[nf][1], h0, l0);
        split2(Cc[nf][2], Cc[nf][3], h1, l1);
        *(uint32_t*)(Ch + o1) = h0;
        *(uint32_t*)(Cl + o1) = l0;
        *(uint32_t*)(Ch + o2) = h1;
        *(uint32_t*)(Cl + o2) = l1;
    }
}

// ---------------------------------------------------------------------------
extern "C" void kernel_launch(void* const* d_in, const int* in_sizes, int n_in,
                              void* d_out, int out_size)
{
    const float* x  = (const float*)d_in[0];
    const int*   mask = (const int*)d_in[1];
    const float* wq = (const float*)d_in[2];
    const float* bq = (const float*)d_in[3];
    const float* wk = (const float*)d_in[4];
    const float* bk = (const float*)d_in[5];
    const float* wv = (const float*)d_in[6];
    const float* bv = (const float*)d_in[7];
    const float* wo = (const float*)d_in[8];
    const float* bo = (const float*)d_in[9];

    float* out   = (float*)d_out;
    float* probs = (float*)d_out + (size_t)M_TOK * E_DIM;

    __nv_bfloat16 *xh, *xl, *qh, *ql, *kh, *kl, *vh, *vl, *ch, *cl, *wh, *wl, *xbh, *xbl;
    cudaGetSymbolAddress((void**)&xh, g_xh);
    cudaGetSymbolAddress((void**)&xl, g_xl);
    cudaGetSymbolAddress((void**)&qh, g_qh);
    cudaGetSymbolAddress((void**)&ql, g_ql);
    cudaGetSymbolAddress((void**)&kh, g_kh);
    cudaGetSymbolAddress((void**)&kl, g_kl);
    cudaGetSymbolAddress((void**)&vh, g_vh);
    cudaGetSymbolAddress((void**)&vl, g_vl);
    cudaGetSymbolAddress((void**)&ch, g_ch);
    cudaGetSymbolAddress((void**)&cl, g_cl);
    cudaGetSymbolAddress((void**)&wh, g_wh);
    cudaGetSymbolAddress((void**)&wl, g_wl);
    cudaGetSymbolAddress((void**)&xbh, g_xbh);
    cudaGetSymbolAddress((void**)&xbl, g_xbl);

    static cudaStream_t s2 = nullptr;
    static cudaEvent_t evF = nullptr, evX = nullptr, evQ = nullptr, evB = nullptr;
    static bool attr_set = false;
    if (!attr_set) {
        cudaFuncSetAttribute(attn_kernel, cudaFuncAttributeMaxDynamicSharedMemorySize,
                             ATT_SMEM);
        cudaFuncSetAttribute(gemm_qkv_kernel, cudaFuncAttributeMaxDynamicSharedMemorySize,
                             GEMM_SMEM);
        cudaFuncSetAttribute(gemm_out_kernel, cudaFuncAttributeMaxDynamicSharedMemorySize,
                             GEMM_SMEM);
        cudaFuncSetAttribute(gemm_outm_kernel, cudaFuncAttributeMaxDynamicSharedMemorySize,
                             GEMM_SMEM);
        cudaStreamCreateWithFlags(&s2, cudaStreamNonBlocking);
        cudaEventCreateWithFlags(&evF, cudaEventDisableTiming);
        cudaEventCreateWithFlags(&evX, cudaEventDisableTiming);
        cudaEventCreateWithFlags(&evQ, cudaEventDisableTiming);
        cudaEventCreateWithFlags(&evB, cudaEventDisableTiming);
        attr_set = true;
    }

    const size_t wo_off = 3 * (size_t)NW_ELEM;

    // fork stream B: xbar (feeds QKV z=3), then masked probs fill
    cudaEventRecord(evF, 0);
    cudaStreamWaitEvent(s2, evF, 0);
    xbar_kernel<<<C_DIM, 256, 0, s2>>>(x, mask, xbh, xbl);
    cudaEventRecord(evX, s2);
    probs_fill_kernel<<<dim3(C_DIM, H_DIM), 256, 0, s2>>>(mask, probs);

    // main chain (prep + split overlap xbar)
    prep_mask_kernel<<<1, 256>>>(mask);
    split_all_kernel<<<4224, 256>>>(x, mask, wq, wk, wv, wo, xh, xl, wh, wl);
    cudaStreamWaitEvent(0, evX, 0);

    dim3 gqkv(E_DIM / BN, C_DIM, 4);        // z=0..2 QKV (exit beyond nu), z=3 Vbar
    gemm_qkv_kernel<<<gqkv, 256, GEMM_SMEM>>>(xh, xl, xbh, xbl, wh, wl, bq, bk, bv,
                                              qh, ql, kh, kl, vh, vl, ch, cl);
    cudaEventRecord(evQ, 0);

    // stream B: masked out row0 + broadcast (depends on Vbar ctx from QKV);
    // overlaps unmasked attention on the main stream.
    cudaStreamWaitEvent(s2, evQ, 0);
    gemm_outm_kernel<<<dim3(E_DIM / BN, 2), 256, GEMM_SMEM, s2>>>(
        ch, cl, wh + wo_off, wl + wo_off, bo, out);
    bcast_out_kernel<<<dim3(C_DIM, R_DIM - 1), 192, 0, s2>>>(mask, out);
    cudaEventRecord(evB, s2);

    // main chain: full-grid attention, then unmasked out-GEMM
    dim3 gattn(C_DIM, H_DIM);
    attn_kernel<<<gattn, 256, ATT_SMEM>>>(qh, ql, kh, kl, vh, vl, mask, probs, ch, cl);

    dim3 gout(E_DIM / BN, C_DIM);           // unmasked tiles only (exit beyond nu)
    gemm_out_kernel<<<gout, 256, GEMM_SMEM>>>(ch, cl, wh + wo_off, wl + wo_off, bo, out);

    // join stream B
    cudaStreamWaitEvent(0, evB, 0);
}